// round 16
// baseline (speedup 1.0000x reference)
#include <cuda_runtime.h>
#include <cuda_fp16.h>
#include <math.h>
#include <stdint.h>

#define Bsz 64
#define Ssz 128
#define Hsz 1024
#define Vsz 32000
#define Tsz 10
#define H3  (3*Hsz)
#define SPL 8
#define NBLK 256

#define BIG_SMEM   (2*(128+128)*36*4)
#define SMALL_SMEM (2*(64+128)*36*4)

// ---------------- device scratch ----------------
__device__ __half g_Uk   [Bsz*Ssz*Hsz];      // fp16 Uk (validated)
__device__ __half g_histh[Tsz*Bsz*Hsz];      // fp16 hist for logits GEMM
__device__ float g_h0   [Bsz*Hsz];
__device__ float g_hist [Tsz*Bsz*Hsz];
__device__ float g_xall [Tsz*Bsz*2*Hsz];     // [emb | ctx] per step
__device__ float g_giemb[Tsz*Bsz*H3];        // emb half of gi (+b_ih), hoisted
__device__ float g_qp   [SPL*Bsz*Hsz];
__device__ float g_gip  [SPL*Bsz*H3];
__device__ float g_ghp  [SPL*Bsz*H3];
__device__ float g_sc   [Bsz*Ssz];

__device__ unsigned int g_barGen;
__device__ unsigned int g_barCnt;

// ---------------- helpers ----------------
__device__ __forceinline__ uint32_t to_tf32u(float x) {
    uint32_t u;
    asm("cvt.rna.tf32.f32 %0, %1;" : "=r"(u) : "f"(x));
    return u;
}
__device__ __forceinline__ float tanh_fast(float x) {
    float y;
    asm("tanh.approx.f32 %0, %1;" : "=f"(y) : "f"(x));
    return y;
}
__device__ __forceinline__ float fexp(float x) {
    float y = fmaxf(x, -80.f) * 1.44269504f;
    int ni = __float2int_rn(y);
    float t = (y - (float)ni) * 0.69314718056f;
    float p = 1.f + t*(1.f + t*(0.5f + t*(0.16666667f + t*(0.041666668f
              + t*(0.0083333338f + t*0.0013888889f)))));
    return p * __int_as_float((ni + 127) << 23);
}
__device__ __forceinline__ void mma_tf32(float c[4],
                                         uint32_t a0, uint32_t a1, uint32_t a2, uint32_t a3,
                                         uint32_t b0, uint32_t b1)
{
    asm volatile(
        "mma.sync.aligned.m16n8k8.row.col.f32.tf32.tf32.f32 "
        "{%0,%1,%2,%3}, {%4,%5,%6,%7}, {%8,%9}, {%0,%1,%2,%3};"
        : "+f"(c[0]), "+f"(c[1]), "+f"(c[2]), "+f"(c[3])
        : "r"(a0), "r"(a1), "r"(a2), "r"(a3), "r"(b0), "r"(b1));
}
__device__ __forceinline__ void mma_f16(float c[4],
                                        uint32_t a0, uint32_t a1, uint32_t a2, uint32_t a3,
                                        uint32_t b0, uint32_t b1)
{
    asm volatile(
        "mma.sync.aligned.m16n8k16.row.col.f32.f16.f16.f32 "
        "{%0,%1,%2,%3}, {%4,%5,%6,%7}, {%8,%9}, {%0,%1,%2,%3};"
        : "+f"(c[0]), "+f"(c[1]), "+f"(c[2]), "+f"(c[3])
        : "r"(a0), "r"(a1), "r"(a2), "r"(a3), "r"(b0), "r"(b1));
}
__device__ __forceinline__ void cp16(const void* s, const void* g) {
    uint32_t sa = (uint32_t)__cvta_generic_to_shared(s);
    asm volatile("cp.async.cg.shared.global [%0], [%1], 16;\n" :: "r"(sa), "l"(g) : "memory");
}
__device__ __forceinline__ void cp_commit() { asm volatile("cp.async.commit_group;\n" ::: "memory"); }
__device__ __forceinline__ void cp_wait0()  { asm volatile("cp.async.wait_group 0;\n" ::: "memory"); }
__device__ __forceinline__ void cp_wait1()  { asm volatile("cp.async.wait_group 1;\n" ::: "memory"); }

// sense-reversing grid barrier, tight L2 poll
__device__ __forceinline__ void grid_sync()
{
    __syncthreads();
    if (threadIdx.x == 0) {
        __threadfence();
        unsigned int gen = *(volatile unsigned int*)&g_barGen;
        if (atomicAdd(&g_barCnt, 1u) == (unsigned)NBLK - 1u) {
            g_barCnt = 0u;
            __threadfence();
            atomicExch(&g_barGen, gen + 1u);
        } else {
            while (*(volatile unsigned int*)&g_barGen == gen) { }
            __threadfence();
        }
    }
    __syncthreads();
}

// ======== BIG GEMM fp32/tf32: 128Mx128N (Uk fp16-out / gi_emb) ========
__global__ __launch_bounds__(256)
void gemm_big(const float* __restrict__ A, int lda,
              const float* __restrict__ W, int ldw,
              const float* __restrict__ bias, float* __restrict__ C,
              int K, int ldc, int outHalf)
{
    extern __shared__ float sm[];
    float (*As)[36] = (float(*)[36])sm;
    float (*Bs)[36] = (float(*)[36])(sm + 2*128*36);

    const int t    = threadIdx.x;
    const int lane = t & 31;
    const int wid  = t >> 5;
    const int wm32 = (wid & 3) * 32;
    const int wn64 = (wid >> 2) * 64;
    const int m0   = blockIdx.z * 128;
    const int n0   = blockIdx.x * 128;
    const int r    = lane >> 2;
    const int c    = lane & 3;

    float acc[2][8][4];
    #pragma unroll
    for (int mi = 0; mi < 2; mi++)
        #pragma unroll
        for (int nt = 0; nt < 8; nt++)
            #pragma unroll
            for (int j = 0; j < 4; j++) acc[mi][nt][j] = 0.f;

    #pragma unroll
    for (int rr = 0; rr < 4; rr++) {
        int idx = rr * 256 + t;
        int m = idx >> 3, kq = idx & 7;
        cp16(&As[m][kq << 2], A + (size_t)(m0 + m) * lda + (kq << 2));
    }
    #pragma unroll
    for (int rr = 0; rr < 4; rr++) {
        int idx = rr * 256 + t;
        int n = idx >> 3, kq = idx & 7;
        cp16(&Bs[n][kq << 2], W + (size_t)(n0 + n) * ldw + (kq << 2));
    }
    cp_commit();

    const int niter = K >> 5;
    for (int i = 0; i < niter; i++) {
        if (i + 1 < niter) {
            const int kb = (i + 1) << 5;
            const int nb = ((i + 1) & 1) * 128;
            #pragma unroll
            for (int rr = 0; rr < 4; rr++) {
                int idx = rr * 256 + t;
                int m = idx >> 3, kq = idx & 7;
                cp16(&As[nb + m][kq << 2], A + (size_t)(m0 + m) * lda + kb + (kq << 2));
            }
            #pragma unroll
            for (int rr = 0; rr < 4; rr++) {
                int idx = rr * 256 + t;
                int n = idx >> 3, kq = idx & 7;
                cp16(&Bs[nb + n][kq << 2], W + (size_t)(n0 + n) * ldw + kb + (kq << 2));
            }
            cp_commit();
            cp_wait1();
        } else {
            cp_wait0();
        }
        __syncthreads();

        const int ab = (i & 1) * 128;
        #pragma unroll
        for (int kc = 0; kc < 4; kc++) {
            const int k8 = kc << 3;
            uint32_t a[2][4];
            #pragma unroll
            for (int mi = 0; mi < 2; mi++) {
                const int mr = ab + wm32 + (mi << 4) + r;
                a[mi][0] = to_tf32u(As[mr    ][k8 + c    ]);
                a[mi][1] = to_tf32u(As[mr + 8][k8 + c    ]);
                a[mi][2] = to_tf32u(As[mr    ][k8 + c + 4]);
                a[mi][3] = to_tf32u(As[mr + 8][k8 + c + 4]);
            }
            #pragma unroll
            for (int nt = 0; nt < 8; nt++) {
                const int nr = ab + wn64 + (nt << 3) + r;
                uint32_t b0 = to_tf32u(Bs[nr][k8 + c    ]);
                uint32_t b1 = to_tf32u(Bs[nr][k8 + c + 4]);
                mma_tf32(acc[0][nt], a[0][0], a[0][1], a[0][2], a[0][3], b0, b1);
                mma_tf32(acc[1][nt], a[1][0], a[1][1], a[1][2], a[1][3], b0, b1);
            }
        }
        __syncthreads();
    }

    const int c2 = c << 1;
    #pragma unroll
    for (int mi = 0; mi < 2; mi++) {
        int m  = m0 + wm32 + (mi << 4) + r;
        int m2 = m + 8;
        #pragma unroll
        for (int nt = 0; nt < 8; nt++) {
            const int n = n0 + wn64 + (nt << 3) + c2;
            float b0 = bias[n], b1 = bias[n + 1];
            if (outHalf) {
                __half* Ch = (__half*)C;
                *(__half2*)(Ch + (size_t)m  * ldc + n) =
                    __floats2half2_rn(acc[mi][nt][0] + b0, acc[mi][nt][1] + b1);
                *(__half2*)(Ch + (size_t)m2 * ldc + n) =
                    __floats2half2_rn(acc[mi][nt][2] + b0, acc[mi][nt][3] + b1);
            } else {
                *(float2*)(C + (size_t)m  * ldc + n) =
                    make_float2(acc[mi][nt][0] + b0, acc[mi][nt][1] + b1);
                *(float2*)(C + (size_t)m2 * ldc + n) =
                    make_float2(acc[mi][nt][2] + b0, acc[mi][nt][3] + b1);
            }
        }
    }
}

// ======== LOGITS GEMM: A fp16 (histh), B staged inline from fp32 out_W ========
// grid (5,1,250): x=m-tile (co-resident blocks share n-tile's B in L2).
// B path: LDG float4 -> cvt fp16 -> STS (software-pipelined across mma).
__global__ __launch_bounds__(256)
void gemm_lf(const __half* __restrict__ A, const float* __restrict__ W,
             const float* __restrict__ bias, float* __restrict__ C)
{
    __shared__ __align__(16) __half As[2][128][40];
    __shared__ __align__(16) __half Bs[2][128][40];

    const int t    = threadIdx.x;
    const int lane = t & 31;
    const int wid  = t >> 5;
    const int wm32 = (wid & 3) * 32;
    const int wn64 = (wid >> 2) * 64;
    const int m0   = blockIdx.x * 128;
    const int n0   = blockIdx.z * 128;
    const int r    = lane >> 2;
    const int c    = lane & 3;
    const int c2   = c << 1;

    // B staging: each thread owns half a row per chunk (16 halves)
    const int brow = t >> 1;
    const int bcol = (t & 1) << 4;
    const float* Wrow = W + (size_t)(n0 + brow) * Hsz + bcol;

    float acc[2][8][4];
    #pragma unroll
    for (int mi = 0; mi < 2; mi++)
        #pragma unroll
        for (int nt = 0; nt < 8; nt++)
            #pragma unroll
            for (int j = 0; j < 4; j++) acc[mi][nt][j] = 0.f;

    float4 bv[4];
    auto loadB = [&](int kb) {
        #pragma unroll
        for (int j = 0; j < 4; j++) bv[j] = *(const float4*)(Wrow + kb + j * 4);
    };
    auto storeB = [&](int buf) {
        uint32_t h[8];
        #pragma unroll
        for (int j = 0; j < 4; j++) {
            __half2 lo = __floats2half2_rn(bv[j].x, bv[j].y);
            __half2 hi = __floats2half2_rn(bv[j].z, bv[j].w);
            h[2*j]   = *(uint32_t*)&lo;
            h[2*j+1] = *(uint32_t*)&hi;
        }
        uint4 p0 = make_uint4(h[0], h[1], h[2], h[3]);
        uint4 p1 = make_uint4(h[4], h[5], h[6], h[7]);
        *(uint4*)(&Bs[buf][brow][bcol])     = p0;
        *(uint4*)(&Bs[buf][brow][bcol + 8]) = p1;
    };

    // prologue: chunk 0
    #pragma unroll
    for (int rr = 0; rr < 2; rr++) {
        int idx = rr * 256 + t;
        int m = idx >> 2, kq = idx & 3;
        cp16(&As[0][m][kq << 3], A + (size_t)(m0 + m) * Hsz + (kq << 3));
    }
    cp_commit();
    loadB(0);
    storeB(0);
    cp_wait0();
    __syncthreads();

    const int niter = Hsz >> 5;   // 32
    for (int i = 0; i < niter; i++) {
        const int ab = i & 1;
        if (i + 1 < niter) {
            const int kb = (i + 1) << 5;
            #pragma unroll
            for (int rr = 0; rr < 2; rr++) {
                int idx = rr * 256 + t;
                int m = idx >> 2, kq = idx & 3;
                cp16(&As[(i + 1) & 1][m][kq << 3], A + (size_t)(m0 + m) * Hsz + kb + (kq << 3));
            }
            cp_commit();
            loadB(kb);          // LDGs in flight across the mma below
        }

        #pragma unroll
        for (int ks = 0; ks < 2; ks++) {
            const int k16 = ks << 4;
            uint32_t a[2][4];
            #pragma unroll
            for (int mi = 0; mi < 2; mi++) {
                const int mr = wm32 + (mi << 4) + r;
                a[mi][0] = *(const uint32_t*)&As[ab][mr    ][k16 + c2    ];
                a[mi][1] = *(const uint32_t*)&As[ab][mr + 8][k16 + c2    ];
                a[mi][2] = *(const uint32_t*)&As[ab][mr    ][k16 + c2 + 8];
                a[mi][3] = *(const uint32_t*)&As[ab][mr + 8][k16 + c2 + 8];
            }
            #pragma unroll
            for (int nt = 0; nt < 8; nt++) {
                const int nr = wn64 + (nt << 3) + r;
                uint32_t b0 = *(const uint32_t*)&Bs[ab][nr][k16 + c2    ];
                uint32_t b1 = *(const uint32_t*)&Bs[ab][nr][k16 + c2 + 8];
                mma_f16(acc[0][nt], a[0][0], a[0][1], a[0][2], a[0][3], b0, b1);
                mma_f16(acc[1][nt], a[1][0], a[1][1], a[1][2], a[1][3], b0, b1);
            }
        }

        if (i + 1 < niter) {
            storeB((i + 1) & 1);
            cp_wait0();
        }
        __syncthreads();
    }

    #pragma unroll
    for (int mi = 0; mi < 2; mi++) {
        int mlog  = m0 + wm32 + (mi << 4) + r;
        int mlog2 = mlog + 8;
        int m  = (mlog  & 63) * Tsz + (mlog  >> 6);
        int m2 = (mlog2 & 63) * Tsz + (mlog2 >> 6);
        #pragma unroll
        for (int nt = 0; nt < 8; nt++) {
            const int n = n0 + wn64 + (nt << 3) + c2;
            float b0 = bias[n], b1 = bias[n + 1];
            *(float2*)(C + (size_t)m  * Vsz + n) =
                make_float2(acc[mi][nt][0] + b0, acc[mi][nt][1] + b1);
            *(float2*)(C + (size_t)m2 * Vsz + n) =
                make_float2(acc[mi][nt][2] + b0, acc[mi][nt][3] + b1);
        }
    }
}

// ======== small GEMM tile core (inside mega): 64Mx128N, K-slice (tf32) ========
__device__ void small_core(
    const float* __restrict__ A, int lda, const float* __restrict__ W, int ldw,
    float* __restrict__ Cp, int N, int kb0, int kPerSplit, int n0, float* sm)
{
    float (*As)[36] = (float(*)[36])sm;
    float (*Bs)[36] = (float(*)[36])(sm + 2*64*36);

    const int t    = threadIdx.x;
    const int lane = t & 31;
    const int wid  = t >> 5;
    const int wm16 = (wid & 3) * 16;
    const int wn64 = (wid >> 2) * 64;
    const int r    = lane >> 2;
    const int c    = lane & 3;

    float acc[8][4];
    #pragma unroll
    for (int i = 0; i < 8; i++)
        #pragma unroll
        for (int j = 0; j < 4; j++) acc[i][j] = 0.f;

    #pragma unroll
    for (int rr = 0; rr < 2; rr++) {
        int idx = rr * 256 + t;
        int m = idx >> 3, kq = idx & 7;
        cp16(&As[m][kq << 2], A + (size_t)m * lda + kb0 + (kq << 2));
    }
    #pragma unroll
    for (int rr = 0; rr < 4; rr++) {
        int idx = rr * 256 + t;
        int n = idx >> 3, kq = idx & 7;
        cp16(&Bs[n][kq << 2], W + (size_t)(n0 + n) * ldw + kb0 + (kq << 2));
    }
    cp_commit();

    const int niter = kPerSplit >> 5;
    for (int i = 0; i < niter; i++) {
        if (i + 1 < niter) {
            const int kb = kb0 + ((i + 1) << 5);
            const int ao = ((i + 1) & 1) * 64;
            const int bo = ((i + 1) & 1) * 128;
            #pragma unroll
            for (int rr = 0; rr < 2; rr++) {
                int idx = rr * 256 + t;
                int m = idx >> 3, kq = idx & 7;
                cp16(&As[ao + m][kq << 2], A + (size_t)m * lda + kb + (kq << 2));
            }
            #pragma unroll
            for (int rr = 0; rr < 4; rr++) {
                int idx = rr * 256 + t;
                int n = idx >> 3, kq = idx & 7;
                cp16(&Bs[bo + n][kq << 2], W + (size_t)(n0 + n) * ldw + kb + (kq << 2));
            }
            cp_commit();
            cp_wait1();
        } else {
            cp_wait0();
        }
        __syncthreads();

        const int ao = (i & 1) * 64;
        const int bo = (i & 1) * 128;
        #pragma unroll
        for (int kc = 0; kc < 4; kc++) {
            const int k8 = kc << 3;
            uint32_t a0 = to_tf32u(As[ao + wm16 + r    ][k8 + c    ]);
            uint32_t a1 = to_tf32u(As[ao + wm16 + r + 8][k8 + c    ]);
            uint32_t a2 = to_tf32u(As[ao + wm16 + r    ][k8 + c + 4]);
            uint32_t a3 = to_tf32u(As[ao + wm16 + r + 8][k8 + c + 4]);
            #pragma unroll
            for (int nt = 0; nt < 8; nt++) {
                const int nr = bo + wn64 + (nt << 3) + r;
                uint32_t b0 = to_tf32u(Bs[nr][k8 + c    ]);
                uint32_t b1 = to_tf32u(Bs[nr][k8 + c + 4]);
                mma_tf32(acc[nt], a0, a1, a2, a3, b0, b1);
            }
        }
        __syncthreads();
    }

    const int c2 = c << 1;
    #pragma unroll
    for (int nt = 0; nt < 8; nt++) {
        const int n = n0 + wn64 + (nt << 3) + c2;
        const int m = wm16 + r;
        *(float2*)(Cp + (size_t)m       * N + n) = make_float2(acc[nt][0], acc[nt][1]);
        *(float2*)(Cp + (size_t)(m + 8) * N + n) = make_float2(acc[nt][2], acc[nt][3]);
    }
}

// ======== persistent mega kernel (round-11 proven core; hT write folded) ========
__global__ __launch_bounds__(256, 2)
void mega_k(const float* __restrict__ enc,
            const float* __restrict__ Wa_w, const float* __restrict__ Wa_b,
            const float* __restrict__ Va,   const float* __restrict__ Vab,
            const float* __restrict__ W_ih, const float* __restrict__ W_hh,
            const float* __restrict__ b_hh,
            float* __restrict__ attns, float* __restrict__ out_h)
{
    extern __shared__ float sm[];
    const int bid = blockIdx.x;
    const int tid = threadIdx.x;
    const int wid = tid >> 5;
    const int lane = tid & 31;
    const int gtid = bid * 256 + tid;
    const int gstride = NBLK * 256;

    const __half* Uk = g_Uk;
    float* hist  = g_hist;
    float* xall  = g_xall;
    float* giemb = g_giemb;
    float* qP    = g_qp;
    float* giP   = g_gip;
    float* ghP   = g_ghp;
    float* scv   = g_sc;

    for (int t = 0; t < Tsz; t++) {
        const float* h  = (t == 0) ? g_h0 : hist + (size_t)(t - 1) * Bsz * Hsz;
        float* x_t = xall + (size_t)t * Bsz * 2 * Hsz;

        // ---- A: q partials (64 jobs) + gh partials (192 jobs) ----
        if (bid < 64) {
            int spl = bid & 7, nt = bid >> 3;
            small_core(h, Hsz, Wa_w, Hsz, qP + (size_t)spl * Bsz * Hsz,
                       Hsz, spl * 128, 128, nt * 128, sm);
        } else {
            int j = bid - 64;
            int spl = j & 7, nt = j >> 3;
            small_core(h, Hsz, W_hh, Hsz, ghP + (size_t)spl * Bsz * H3,
                       H3, spl * 128, 128, nt * 128, sm);
        }
        grid_sync();

        // ---- C: scores (q reduced from partials into smem; Uk fp16) ----
        {
            const int b = bid >> 2;
            __syncthreads();
            for (int i = tid; i < Hsz; i += 256) {
                float a = Wa_b[i];
                #pragma unroll
                for (int p = 0; p < SPL; p++)
                    a += qP[(size_t)p * Bsz * Hsz + b * Hsz + i];
                sm[i] = a;
            }
            __syncthreads();
            #pragma unroll
            for (int jj = 0; jj < 4; jj++) {
                const int sg = (bid & 3) * 4 + jj;
                const int s = sg * 8 + wid;
                const __half2* ukr = (const __half2*)(Uk + ((size_t)b * Ssz + s) * Hsz);
                float a = 0.f;
                #pragma unroll
                for (int q8 = 0; q8 < 8; q8++) {
                    const int hh = lane * 4 + q8 * 128;
                    uint2 u2 = *(const uint2*)(ukr + (hh >> 1));
                    float2 f0 = __half22float2(*(__half2*)&u2.x);
                    float2 f1 = __half22float2(*(__half2*)&u2.y);
                    float4 qq = *(const float4*)(&sm[hh]);
                    float4 vv = *(const float4*)(Va + hh);
                    a += vv.x * tanh_fast(qq.x + f0.x);
                    a += vv.y * tanh_fast(qq.y + f0.y);
                    a += vv.z * tanh_fast(qq.z + f1.x);
                    a += vv.w * tanh_fast(qq.w + f1.y);
                }
                #pragma unroll
                for (int o = 16; o; o >>= 1) a += __shfl_xor_sync(0xffffffffu, a, o);
                if (!lane) scv[b * Ssz + s] = a + Vab[0];
            }
        }
        grid_sync();

        // ---- D: softmax + attns + ctx ----
        {
            const int b = bid >> 2, hc = bid & 3;
            float* wsm = sm;
            float* red = sm + 128;
            __syncthreads();
            if (tid < 128) wsm[tid] = scv[b * Ssz + tid];
            __syncthreads();
            float v = 0.f, e = 0.f;
            if (tid < 128) {
                v = wsm[tid];
                float m = v;
                #pragma unroll
                for (int o = 16; o; o >>= 1) m = fmaxf(m, __shfl_xor_sync(0xffffffffu, m, o));
                if (!lane) red[wid] = m;
            }
            __syncthreads();
            float mx = fmaxf(fmaxf(red[0], red[1]), fmaxf(red[2], red[3]));
            if (tid < 128) {
                e = expf(v - mx);
                float sme = e;
                #pragma unroll
                for (int o = 16; o; o >>= 1) sme += __shfl_xor_sync(0xffffffffu, sme, o);
                if (!lane) red[4 + wid] = sme;
            }
            __syncthreads();
            float ssum = red[4] + red[5] + red[6] + red[7];
            if (tid < 128) {
                float w = e / ssum;
                wsm[tid] = w;
                if (hc == 0) attns[((size_t)b * Tsz + t) * Ssz + tid] = w;
            }
            __syncthreads();
            const int hh = hc * 256 + tid;
            const float* Eb = enc + (size_t)b * Ssz * Hsz + hh;
            float acc = 0.f;
            #pragma unroll 8
            for (int s2 = 0; s2 < Ssz; s2++) acc = fmaf(wsm[s2], Eb[(size_t)s2 * Hsz], acc);
            x_t[b * 2 * Hsz + Hsz + hh] = acc;
        }
        grid_sync();

        // ---- E: gi_ctx partials (192 jobs) ----
        if (bid < 192) {
            int spl = bid & 7, nt = bid >> 3;
            small_core(x_t + Hsz, 2 * Hsz, W_ih + Hsz, 2 * Hsz,
                       giP + (size_t)spl * Bsz * H3, H3, spl * 128, 128, nt * 128, sm);
        }
        grid_sync();

        // ---- F: gates -> hist[t] (+fp16 copy; +out_h on final step) ----
        for (int i = gtid; i < Bsz * Hsz; i += gstride) {
            const int b = i >> 10, jj = i & 1023;
            const int row = t * Bsz + b;
            float gr = giemb[(size_t)row * H3 + jj];
            float gz = giemb[(size_t)row * H3 + Hsz + jj];
            float gn = giemb[(size_t)row * H3 + 2 * Hsz + jj];
            float hr = b_hh[jj], hz = b_hh[Hsz + jj], hn3 = b_hh[2 * Hsz + jj];
            const int base = b * H3 + jj;
            #pragma unroll
            for (int p = 0; p < SPL; p++) {
                const float* gp = giP + (size_t)p * Bsz * H3 + base;
                gr += gp[0]; gz += gp[Hsz]; gn += gp[2 * Hsz];
                const float* hp = ghP + (size_t)p * Bsz * H3 + base;
                hr += hp[0]; hz += hp[Hsz]; hn3 += hp[2 * Hsz];
            }
            float r = 1.f / (1.f + expf(-(gr + hr)));
            float z = 1.f / (1.f + expf(-(gz + hz)));
            float n = tanhf(gn + r * hn3);
            float out = (1.f - z) * n + z * h[i];
            hist[(size_t)t * Bsz * Hsz + i] = out;
            g_histh[(size_t)t * Bsz * Hsz + i] = __float2half(out);
            if (t == Tsz - 1) out_h[i] = out;
        }
        grid_sync();
    }
}

// ======== init / log_softmax ========
__global__ void init_k(const float* __restrict__ hidden, float* __restrict__ h0,
                       const float* __restrict__ embW, const int* __restrict__ target,
                       float* __restrict__ xall)
{
    const int idx = blockIdx.x * 256 + threadIdx.x;
    const int t = idx / (Bsz * Hsz);
    const int rem = idx - t * (Bsz * Hsz);
    const int b = rem >> 10, h = rem & 1023;
    const int tok = (t == 0) ? 0 : target[b * Tsz + (t - 1)];
    xall[(size_t)t * Bsz * 2 * Hsz + b * 2 * Hsz + h] = embW[(size_t)tok * Hsz + h];
    if (idx < Bsz * Hsz) h0[idx] = hidden[idx];
}

__global__ __launch_bounds__(512)
void lsm_k(float* __restrict__ out)
{
    __shared__ float redm[16], reds[16];
    float4* p = (float4*)(out + (size_t)blockIdx.x * Vsz);
    const int NV4 = Vsz / 4;
    const int tid = threadIdx.x;

    float m = -3.4e38f, s = 0.f;
    for (int i = tid; i < NV4; i += 512) {
        float4 v = p[i];
        float m4 = fmaxf(fmaxf(v.x, v.y), fmaxf(v.z, v.w));
        float nm = fmaxf(m, m4);
        s = s * fexp(m - nm)
          + fexp(v.x - nm) + fexp(v.y - nm) + fexp(v.z - nm) + fexp(v.w - nm);
        m = nm;
    }
    #pragma unroll
    for (int o = 16; o; o >>= 1) {
        float mo = __shfl_xor_sync(0xffffffffu, m, o);
        float so = __shfl_xor_sync(0xffffffffu, s, o);
        float nm = fmaxf(m, mo);
        s = s * fexp(m - nm) + so * fexp(mo - nm);
        m = nm;
    }
    if ((tid & 31) == 0) { redm[tid >> 5] = m; reds[tid >> 5] = s; }
    __syncthreads();
    m = redm[0]; s = reds[0];
    #pragma unroll
    for (int w = 1; w < 16; w++) {
        float mo = redm[w], so = reds[w];
        float nm = fmaxf(m, mo);
        s = s * fexp(m - nm) + so * fexp(mo - nm);
        m = nm;
    }
    const float lse = m + logf(s);

    for (int i = tid; i < NV4; i += 512) {
        float4 v = p[i];
        v.x -= lse; v.y -= lse; v.z -= lse; v.w -= lse;
        p[i] = v;
    }
}

// ---------------- launch ----------------
extern "C" void kernel_launch(void* const* d_in, const int* in_sizes, int n_in,
                              void* d_out, int out_size)
{
    const float* enc    = (const float*)d_in[0];
    const float* hidden = (const float*)d_in[1];
    const int*   target = (const int*)  d_in[2];
    const float* embW   = (const float*)d_in[3];
    const float* Wa_w   = (const float*)d_in[4];
    const float* Wa_b   = (const float*)d_in[5];
    const float* Ua_w   = (const float*)d_in[6];
    const float* Ua_b   = (const float*)d_in[7];
    const float* Va_w   = (const float*)d_in[8];
    const float* Va_b   = (const float*)d_in[9];
    const float* W_ih   = (const float*)d_in[10];
    const float* W_hh   = (const float*)d_in[11];
    const float* b_ih   = (const float*)d_in[12];
    const float* b_hh   = (const float*)d_in[13];
    const float* out_W  = (const float*)d_in[14];
    const float* out_b  = (const float*)d_in[15];

    float* out_lp = (float*)d_out;                        // [B,T,V]
    float* out_h  = out_lp + (size_t)Bsz * Tsz * Vsz;     // [1,B,H]
    float* out_at = out_h + (size_t)Bsz * Hsz;            // [B,T,S]

    __half *Uk, *histh;
    float *h0, *hist, *xall, *giemb;
    cudaGetSymbolAddress((void**)&Uk,    g_Uk);
    cudaGetSymbolAddress((void**)&histh, g_histh);
    cudaGetSymbolAddress((void**)&h0,    g_h0);
    cudaGetSymbolAddress((void**)&hist,  g_hist);
    cudaGetSymbolAddress((void**)&xall,  g_xall);
    cudaGetSymbolAddress((void**)&giemb, g_giemb);

    cudaFuncSetAttribute(gemm_big, cudaFuncAttributeMaxDynamicSharedMemorySize, BIG_SMEM);
    cudaFuncSetAttribute(mega_k,   cudaFuncAttributeMaxDynamicSharedMemorySize, SMALL_SMEM);

    // init: h0 + all embedding gathers (no convw pass — lf converts inline)
    init_k<<<(Tsz * Bsz * Hsz) / 256, 256>>>(hidden, h0, embW, target, xall);

    // Uk = enc @ Ua_w^T + Ua_b  -> fp16 output
    gemm_big<<<dim3(Hsz / 128, 1, (Bsz * Ssz) / 128), 256, BIG_SMEM>>>(
        enc, Hsz, Ua_w, Hsz, Ua_b, (float*)Uk, Hsz, Hsz, 1);

    // gi_emb (all steps), single launch: A row stride 2H; W_ih ldw = 2H
    gemm_big<<<dim3(H3 / 128, 1, (Tsz * Bsz) / 128), 256, BIG_SMEM>>>(
        xall, 2 * Hsz, W_ih, 2 * Hsz, b_ih, giemb, Hsz, H3, 0);

    // the whole recurrence in one persistent launch; writes out_h on t=9
    mega_k<<<NBLK, 256, SMALL_SMEM>>>(enc, Wa_w, Wa_b, Va_w, Va_b,
                                      W_ih, W_hh, b_hh, out_at, out_h);

    // batched logits: A fp16, B fp32->fp16 inline; grid (m,1,n) for B L2 reuse
    gemm_lf<<<dim3((Tsz * Bsz) / 128, 1, Vsz / 128), 256>>>(
        histh, out_W, out_b, out_lp);

    lsm_k<<<Bsz * Tsz, 512>>>(out_lp);
}

// round 17
// speedup vs baseline: 1.0703x; 1.0703x over previous
#include <cuda_runtime.h>
#include <cuda_fp16.h>
#include <math.h>
#include <stdint.h>

#define Bsz 64
#define Ssz 128
#define Hsz 1024
#define Vsz 32000
#define Tsz 10
#define H3  (3*Hsz)
#define SPL 8
#define NBLK 256

#define BIG_SMEM   (2*(128+128)*36*4)
#define SMALL_SMEM (2*(64+128)*36*4)

// ---------------- device scratch ----------------
__device__ __half g_Uk   [Bsz*Ssz*Hsz];      // fp16 Uk (validated)
__device__ __half g_outWh[(size_t)Vsz*Hsz];  // fp16 out_W
__device__ __half g_histh[Tsz*Bsz*Hsz];      // fp16 hist for logits GEMM
__device__ float g_h0   [Bsz*Hsz];
__device__ float g_hist [Tsz*Bsz*Hsz];
__device__ float g_xall [Tsz*Bsz*2*Hsz];     // [emb | ctx] per step
__device__ float g_giemb[Tsz*Bsz*H3];        // emb half of gi (+b_ih), hoisted
__device__ float g_qp   [SPL*Bsz*Hsz];
__device__ float g_gip  [SPL*Bsz*H3];
__device__ float g_ghp  [SPL*Bsz*H3];
__device__ float g_sc   [Bsz*Ssz];

__device__ unsigned int g_barGen;
__device__ unsigned int g_barCnt;
__device__ unsigned int g_bsync[Bsz];        // per-b C->D arrive counters (reset in init_k)

// ---------------- helpers ----------------
__device__ __forceinline__ uint32_t to_tf32u(float x) {
    uint32_t u;
    asm("cvt.rna.tf32.f32 %0, %1;" : "=r"(u) : "f"(x));
    return u;
}
__device__ __forceinline__ float tanh_fast(float x) {
    float y;
    asm("tanh.approx.f32 %0, %1;" : "=f"(y) : "f"(x));
    return y;
}
__device__ __forceinline__ float fexp(float x) {
    float y = fmaxf(x, -80.f) * 1.44269504f;
    int ni = __float2int_rn(y);
    float t = (y - (float)ni) * 0.69314718056f;
    float p = 1.f + t*(1.f + t*(0.5f + t*(0.16666667f + t*(0.041666668f
              + t*(0.0083333338f + t*0.0013888889f)))));
    return p * __int_as_float((ni + 127) << 23);
}
__device__ __forceinline__ void mma_tf32(float c[4],
                                         uint32_t a0, uint32_t a1, uint32_t a2, uint32_t a3,
                                         uint32_t b0, uint32_t b1)
{
    asm volatile(
        "mma.sync.aligned.m16n8k8.row.col.f32.tf32.tf32.f32 "
        "{%0,%1,%2,%3}, {%4,%5,%6,%7}, {%8,%9}, {%0,%1,%2,%3};"
        : "+f"(c[0]), "+f"(c[1]), "+f"(c[2]), "+f"(c[3])
        : "r"(a0), "r"(a1), "r"(a2), "r"(a3), "r"(b0), "r"(b1));
}
__device__ __forceinline__ void mma_f16(float c[4],
                                        uint32_t a0, uint32_t a1, uint32_t a2, uint32_t a3,
                                        uint32_t b0, uint32_t b1)
{
    asm volatile(
        "mma.sync.aligned.m16n8k16.row.col.f32.f16.f16.f32 "
        "{%0,%1,%2,%3}, {%4,%5,%6,%7}, {%8,%9}, {%0,%1,%2,%3};"
        : "+f"(c[0]), "+f"(c[1]), "+f"(c[2]), "+f"(c[3])
        : "r"(a0), "r"(a1), "r"(a2), "r"(a3), "r"(b0), "r"(b1));
}
__device__ __forceinline__ void cp16(const void* s, const void* g) {
    uint32_t sa = (uint32_t)__cvta_generic_to_shared(s);
    asm volatile("cp.async.cg.shared.global [%0], [%1], 16;\n" :: "r"(sa), "l"(g) : "memory");
}
__device__ __forceinline__ void cp_commit() { asm volatile("cp.async.commit_group;\n" ::: "memory"); }
__device__ __forceinline__ void cp_wait0()  { asm volatile("cp.async.wait_group 0;\n" ::: "memory"); }
__device__ __forceinline__ void cp_wait1()  { asm volatile("cp.async.wait_group 1;\n" ::: "memory"); }

// sense-reversing grid barrier, tight L2 poll
__device__ __forceinline__ void grid_sync()
{
    __syncthreads();
    if (threadIdx.x == 0) {
        __threadfence();
        unsigned int gen = *(volatile unsigned int*)&g_barGen;
        if (atomicAdd(&g_barCnt, 1u) == (unsigned)NBLK - 1u) {
            g_barCnt = 0u;
            __threadfence();
            atomicExch(&g_barGen, gen + 1u);
        } else {
            while (*(volatile unsigned int*)&g_barGen == gen) { }
            __threadfence();
        }
    }
    __syncthreads();
}

// ======== BIG GEMM core (device): 128Mx128N tf32, cp.async 2-stage ========
__device__ void big_core(const float* __restrict__ A, int lda,
                         const float* __restrict__ W, int ldw,
                         const float* __restrict__ bias, float* __restrict__ C,
                         int K, int ldc, int outHalf, int m0, int n0)
{
    extern __shared__ float sm[];
    float (*As)[36] = (float(*)[36])sm;
    float (*Bs)[36] = (float(*)[36])(sm + 2*128*36);

    const int t    = threadIdx.x;
    const int lane = t & 31;
    const int wid  = t >> 5;
    const int wm32 = (wid & 3) * 32;
    const int wn64 = (wid >> 2) * 64;
    const int r    = lane >> 2;
    const int c    = lane & 3;

    float acc[2][8][4];
    #pragma unroll
    for (int mi = 0; mi < 2; mi++)
        #pragma unroll
        for (int nt = 0; nt < 8; nt++)
            #pragma unroll
            for (int j = 0; j < 4; j++) acc[mi][nt][j] = 0.f;

    #pragma unroll
    for (int rr = 0; rr < 4; rr++) {
        int idx = rr * 256 + t;
        int m = idx >> 3, kq = idx & 7;
        cp16(&As[m][kq << 2], A + (size_t)(m0 + m) * lda + (kq << 2));
    }
    #pragma unroll
    for (int rr = 0; rr < 4; rr++) {
        int idx = rr * 256 + t;
        int n = idx >> 3, kq = idx & 7;
        cp16(&Bs[n][kq << 2], W + (size_t)(n0 + n) * ldw + (kq << 2));
    }
    cp_commit();

    const int niter = K >> 5;
    for (int i = 0; i < niter; i++) {
        if (i + 1 < niter) {
            const int kb = (i + 1) << 5;
            const int nb = ((i + 1) & 1) * 128;
            #pragma unroll
            for (int rr = 0; rr < 4; rr++) {
                int idx = rr * 256 + t;
                int m = idx >> 3, kq = idx & 7;
                cp16(&As[nb + m][kq << 2], A + (size_t)(m0 + m) * lda + kb + (kq << 2));
            }
            #pragma unroll
            for (int rr = 0; rr < 4; rr++) {
                int idx = rr * 256 + t;
                int n = idx >> 3, kq = idx & 7;
                cp16(&Bs[nb + n][kq << 2], W + (size_t)(n0 + n) * ldw + kb + (kq << 2));
            }
            cp_commit();
            cp_wait1();
        } else {
            cp_wait0();
        }
        __syncthreads();

        const int ab = (i & 1) * 128;
        #pragma unroll
        for (int kc = 0; kc < 4; kc++) {
            const int k8 = kc << 3;
            uint32_t a[2][4];
            #pragma unroll
            for (int mi = 0; mi < 2; mi++) {
                const int mr = ab + wm32 + (mi << 4) + r;
                a[mi][0] = to_tf32u(As[mr    ][k8 + c    ]);
                a[mi][1] = to_tf32u(As[mr + 8][k8 + c    ]);
                a[mi][2] = to_tf32u(As[mr    ][k8 + c + 4]);
                a[mi][3] = to_tf32u(As[mr + 8][k8 + c + 4]);
            }
            #pragma unroll
            for (int nt = 0; nt < 8; nt++) {
                const int nr = ab + wn64 + (nt << 3) + r;
                uint32_t b0 = to_tf32u(Bs[nr][k8 + c    ]);
                uint32_t b1 = to_tf32u(Bs[nr][k8 + c + 4]);
                mma_tf32(acc[0][nt], a[0][0], a[0][1], a[0][2], a[0][3], b0, b1);
                mma_tf32(acc[1][nt], a[1][0], a[1][1], a[1][2], a[1][3], b0, b1);
            }
        }
        __syncthreads();
    }

    const int c2 = c << 1;
    #pragma unroll
    for (int mi = 0; mi < 2; mi++) {
        int m  = m0 + wm32 + (mi << 4) + r;
        int m2 = m + 8;
        #pragma unroll
        for (int nt = 0; nt < 8; nt++) {
            const int n = n0 + wn64 + (nt << 3) + c2;
            float b0 = bias[n], b1 = bias[n + 1];
            if (outHalf) {
                __half* Ch = (__half*)C;
                *(__half2*)(Ch + (size_t)m  * ldc + n) =
                    __floats2half2_rn(acc[mi][nt][0] + b0, acc[mi][nt][1] + b1);
                *(__half2*)(Ch + (size_t)m2 * ldc + n) =
                    __floats2half2_rn(acc[mi][nt][2] + b0, acc[mi][nt][3] + b1);
            } else {
                *(float2*)(C + (size_t)m  * ldc + n) =
                    make_float2(acc[mi][nt][0] + b0, acc[mi][nt][1] + b1);
                *(float2*)(C + (size_t)m2 * ldc + n) =
                    make_float2(acc[mi][nt][2] + b0, acc[mi][nt][3] + b1);
            }
        }
    }
}

// Merged pre-GEMMs: Uk (512 blocks) + gi_emb (120 blocks) in ONE launch.
__global__ __launch_bounds__(256)
void gemm_pre(const float* __restrict__ enc, const float* __restrict__ Ua_w,
              const float* __restrict__ Ua_b, __half* __restrict__ Uk,
              const float* __restrict__ xall, const float* __restrict__ W_ih,
              const float* __restrict__ b_ih, float* __restrict__ giemb)
{
    const int bid = blockIdx.x;
    if (bid < 512) {
        // Uk: M=8192 (64 m-tiles), N=1024 (8 n-tiles), fp16 out
        big_core(enc, Hsz, Ua_w, Hsz, Ua_b, (float*)Uk, Hsz, Hsz, 1,
                 (bid >> 3) * 128, (bid & 7) * 128);
    } else {
        // gi_emb: M=640 (5 m-tiles), N=3072 (24 n-tiles); W_ih col-slice ldw=2H
        const int j = bid - 512;
        big_core(xall, 2 * Hsz, W_ih, 2 * Hsz, b_ih, giemb, Hsz, H3, 0,
                 (j / 24) * 128, (j % 24) * 128);
    }
}

// ======== LOGITS GEMM fp16 (round-11/14 validated): 128Mx128N m16n8k16 ========
__global__ __launch_bounds__(256)
void gemm_lh(const __half* __restrict__ A, const __half* __restrict__ W,
             const float* __restrict__ bias, float* __restrict__ C)
{
    __shared__ __half As[2][128][40];
    __shared__ __half Bs[2][128][40];

    const int t    = threadIdx.x;
    const int lane = t & 31;
    const int wid  = t >> 5;
    const int wm32 = (wid & 3) * 32;
    const int wn64 = (wid >> 2) * 64;
    const int m0   = blockIdx.z * 128;
    const int n0   = blockIdx.x * 128;
    const int r    = lane >> 2;
    const int c    = lane & 3;
    const int c2   = c << 1;

    float acc[2][8][4];
    #pragma unroll
    for (int mi = 0; mi < 2; mi++)
        #pragma unroll
        for (int nt = 0; nt < 8; nt++)
            #pragma unroll
            for (int j = 0; j < 4; j++) acc[mi][nt][j] = 0.f;

    #pragma unroll
    for (int rr = 0; rr < 2; rr++) {
        int idx = rr * 256 + t;
        int m = idx >> 2, kq = idx & 3;
        cp16(&As[0][m][kq << 3], A + (size_t)(m0 + m) * Hsz + (kq << 3));
    }
    #pragma unroll
    for (int rr = 0; rr < 2; rr++) {
        int idx = rr * 256 + t;
        int n = idx >> 2, kq = idx & 3;
        cp16(&Bs[0][n][kq << 3], W + (size_t)(n0 + n) * Hsz + (kq << 3));
    }
    cp_commit();

    const int niter = Hsz >> 5;
    for (int i = 0; i < niter; i++) {
        if (i + 1 < niter) {
            const int kb = (i + 1) << 5;
            const int nb = (i + 1) & 1;
            #pragma unroll
            for (int rr = 0; rr < 2; rr++) {
                int idx = rr * 256 + t;
                int m = idx >> 2, kq = idx & 3;
                cp16(&As[nb][m][kq << 3], A + (size_t)(m0 + m) * Hsz + kb + (kq << 3));
            }
            #pragma unroll
            for (int rr = 0; rr < 2; rr++) {
                int idx = rr * 256 + t;
                int n = idx >> 2, kq = idx & 3;
                cp16(&Bs[nb][n][kq << 3], W + (size_t)(n0 + n) * Hsz + kb + (kq << 3));
            }
            cp_commit();
            cp_wait1();
        } else {
            cp_wait0();
        }
        __syncthreads();

        const int ab = i & 1;
        #pragma unroll
        for (int ks = 0; ks < 2; ks++) {
            const int k16 = ks << 4;
            uint32_t a[2][4];
            #pragma unroll
            for (int mi = 0; mi < 2; mi++) {
                const int mr = wm32 + (mi << 4) + r;
                a[mi][0] = *(const uint32_t*)&As[ab][mr    ][k16 + c2    ];
                a[mi][1] = *(const uint32_t*)&As[ab][mr + 8][k16 + c2    ];
                a[mi][2] = *(const uint32_t*)&As[ab][mr    ][k16 + c2 + 8];
                a[mi][3] = *(const uint32_t*)&As[ab][mr + 8][k16 + c2 + 8];
            }
            #pragma unroll
            for (int nt = 0; nt < 8; nt++) {
                const int nr = wn64 + (nt << 3) + r;
                uint32_t b0 = *(const uint32_t*)&Bs[ab][nr][k16 + c2    ];
                uint32_t b1 = *(const uint32_t*)&Bs[ab][nr][k16 + c2 + 8];
                mma_f16(acc[0][nt], a[0][0], a[0][1], a[0][2], a[0][3], b0, b1);
                mma_f16(acc[1][nt], a[1][0], a[1][1], a[1][2], a[1][3], b0, b1);
            }
        }
        __syncthreads();
    }

    #pragma unroll
    for (int mi = 0; mi < 2; mi++) {
        int mlog  = m0 + wm32 + (mi << 4) + r;
        int mlog2 = mlog + 8;
        int m  = (mlog  & 63) * Tsz + (mlog  >> 6);
        int m2 = (mlog2 & 63) * Tsz + (mlog2 >> 6);
        #pragma unroll
        for (int nt = 0; nt < 8; nt++) {
            const int n = n0 + wn64 + (nt << 3) + c2;
            float b0 = bias[n], b1 = bias[n + 1];
            *(float2*)(C + (size_t)m  * Vsz + n) =
                make_float2(acc[mi][nt][0] + b0, acc[mi][nt][1] + b1);
            *(float2*)(C + (size_t)m2 * Vsz + n) =
                make_float2(acc[mi][nt][2] + b0, acc[mi][nt][3] + b1);
        }
    }
}

// ======== small GEMM tile core (inside mega): 64Mx128N, K-slice (tf32) ========
__device__ void small_core(
    const float* __restrict__ A, int lda, const float* __restrict__ W, int ldw,
    float* __restrict__ Cp, int N, int kb0, int kPerSplit, int n0, float* sm)
{
    float (*As)[36] = (float(*)[36])sm;
    float (*Bs)[36] = (float(*)[36])(sm + 2*64*36);

    const int t    = threadIdx.x;
    const int lane = t & 31;
    const int wid  = t >> 5;
    const int wm16 = (wid & 3) * 16;
    const int wn64 = (wid >> 2) * 64;
    const int r    = lane >> 2;
    const int c    = lane & 3;

    float acc[8][4];
    #pragma unroll
    for (int i = 0; i < 8; i++)
        #pragma unroll
        for (int j = 0; j < 4; j++) acc[i][j] = 0.f;

    #pragma unroll
    for (int rr = 0; rr < 2; rr++) {
        int idx = rr * 256 + t;
        int m = idx >> 3, kq = idx & 7;
        cp16(&As[m][kq << 2], A + (size_t)m * lda + kb0 + (kq << 2));
    }
    #pragma unroll
    for (int rr = 0; rr < 4; rr++) {
        int idx = rr * 256 + t;
        int n = idx >> 3, kq = idx & 7;
        cp16(&Bs[n][kq << 2], W + (size_t)(n0 + n) * ldw + kb0 + (kq << 2));
    }
    cp_commit();

    const int niter = kPerSplit >> 5;
    for (int i = 0; i < niter; i++) {
        if (i + 1 < niter) {
            const int kb = kb0 + ((i + 1) << 5);
            const int ao = ((i + 1) & 1) * 64;
            const int bo = ((i + 1) & 1) * 128;
            #pragma unroll
            for (int rr = 0; rr < 2; rr++) {
                int idx = rr * 256 + t;
                int m = idx >> 3, kq = idx & 7;
                cp16(&As[ao + m][kq << 2], A + (size_t)m * lda + kb + (kq << 2));
            }
            #pragma unroll
            for (int rr = 0; rr < 4; rr++) {
                int idx = rr * 256 + t;
                int n = idx >> 3, kq = idx & 7;
                cp16(&Bs[bo + n][kq << 2], W + (size_t)(n0 + n) * ldw + kb + (kq << 2));
            }
            cp_commit();
            cp_wait1();
        } else {
            cp_wait0();
        }
        __syncthreads();

        const int ao = (i & 1) * 64;
        const int bo = (i & 1) * 128;
        #pragma unroll
        for (int kc = 0; kc < 4; kc++) {
            const int k8 = kc << 3;
            uint32_t a0 = to_tf32u(As[ao + wm16 + r    ][k8 + c    ]);
            uint32_t a1 = to_tf32u(As[ao + wm16 + r + 8][k8 + c    ]);
            uint32_t a2 = to_tf32u(As[ao + wm16 + r    ][k8 + c + 4]);
            uint32_t a3 = to_tf32u(As[ao + wm16 + r + 8][k8 + c + 4]);
            #pragma unroll
            for (int nt = 0; nt < 8; nt++) {
                const int nr = bo + wn64 + (nt << 3) + r;
                uint32_t b0 = to_tf32u(Bs[nr][k8 + c    ]);
                uint32_t b1 = to_tf32u(Bs[nr][k8 + c + 4]);
                mma_tf32(acc[nt], a0, a1, a2, a3, b0, b1);
            }
        }
        __syncthreads();
    }

    const int c2 = c << 1;
    #pragma unroll
    for (int nt = 0; nt < 8; nt++) {
        const int n = n0 + wn64 + (nt << 3) + c2;
        const int m = wm16 + r;
        *(float2*)(Cp + (size_t)m       * N + n) = make_float2(acc[nt][0], acc[nt][1]);
        *(float2*)(Cp + (size_t)(m + 8) * N + n) = make_float2(acc[nt][2], acc[nt][3]);
    }
}

// ======== persistent mega kernel: 4 grid barriers + 1 local 4-block sync ========
__global__ __launch_bounds__(256, 2)
void mega_k(const float* __restrict__ enc,
            const float* __restrict__ Wa_w, const float* __restrict__ Wa_b,
            const float* __restrict__ Va,   const float* __restrict__ Vab,
            const float* __restrict__ W_ih, const float* __restrict__ W_hh,
            const float* __restrict__ b_hh,
            float* __restrict__ attns, float* __restrict__ out_h)
{
    extern __shared__ float sm[];
    const int bid = blockIdx.x;
    const int tid = threadIdx.x;
    const int wid = tid >> 5;
    const int lane = tid & 31;
    const int gtid = bid * 256 + tid;
    const int gstride = NBLK * 256;

    const __half* Uk = g_Uk;
    float* hist  = g_hist;
    float* xall  = g_xall;
    float* giemb = g_giemb;
    float* qP    = g_qp;
    float* giP   = g_gip;
    float* ghP   = g_ghp;
    float* scv   = g_sc;

    for (int t = 0; t < Tsz; t++) {
        const float* h  = (t == 0) ? g_h0 : hist + (size_t)(t - 1) * Bsz * Hsz;
        float* x_t = xall + (size_t)t * Bsz * 2 * Hsz;

        // ---- A: q partials (64 jobs) + gh partials (192 jobs) ----
        if (bid < 64) {
            int spl = bid & 7, nt = bid >> 3;
            small_core(h, Hsz, Wa_w, Hsz, qP + (size_t)spl * Bsz * Hsz,
                       Hsz, spl * 128, 128, nt * 128, sm);
        } else {
            int j = bid - 64;
            int spl = j & 7, nt = j >> 3;
            small_core(h, Hsz, W_hh, Hsz, ghP + (size_t)spl * Bsz * H3,
                       H3, spl * 128, 128, nt * 128, sm);
        }
        grid_sync();

        // ---- C: scores (q reduced from partials into smem; Uk fp16) ----
        const int b = bid >> 2;
        {
            __syncthreads();
            for (int i = tid; i < Hsz; i += 256) {
                float a = Wa_b[i];
                #pragma unroll
                for (int p = 0; p < SPL; p++)
                    a += qP[(size_t)p * Bsz * Hsz + b * Hsz + i];
                sm[i] = a;
            }
            __syncthreads();
            #pragma unroll
            for (int jj = 0; jj < 4; jj++) {
                const int sg = (bid & 3) * 4 + jj;
                const int s = sg * 8 + wid;
                const __half2* ukr = (const __half2*)(Uk + ((size_t)b * Ssz + s) * Hsz);
                float a = 0.f;
                #pragma unroll
                for (int q8 = 0; q8 < 8; q8++) {
                    const int hh = lane * 4 + q8 * 128;
                    uint2 u2 = *(const uint2*)(ukr + (hh >> 1));
                    float2 f0 = __half22float2(*(__half2*)&u2.x);
                    float2 f1 = __half22float2(*(__half2*)&u2.y);
                    float4 qq = *(const float4*)(&sm[hh]);
                    float4 vv = *(const float4*)(Va + hh);
                    a += vv.x * tanh_fast(qq.x + f0.x);
                    a += vv.y * tanh_fast(qq.y + f0.y);
                    a += vv.z * tanh_fast(qq.z + f1.x);
                    a += vv.w * tanh_fast(qq.w + f1.y);
                }
                #pragma unroll
                for (int o = 16; o; o >>= 1) a += __shfl_xor_sync(0xffffffffu, a, o);
                if (!lane) scv[b * Ssz + s] = a + Vab[0];
            }
        }
        // ---- local C->D sync: only the 4 blocks sharing this b ----
        __syncthreads();
        if (tid == 0) {
            __threadfence();
            atomicAdd(&g_bsync[b], 1u);
            const unsigned int tgt = 4u * (unsigned)(t + 1);
            while (*(volatile unsigned int*)&g_bsync[b] < tgt) { }
            __threadfence();
        }
        __syncthreads();

        // ---- D: softmax + attns + ctx ----
        {
            const int hc = bid & 3;
            float* wsm = sm;
            float* red = sm + 128;
            if (tid < 128) wsm[tid] = scv[b * Ssz + tid];
            __syncthreads();
            float v = 0.f, e = 0.f;
            if (tid < 128) {
                v = wsm[tid];
                float m = v;
                #pragma unroll
                for (int o = 16; o; o >>= 1) m = fmaxf(m, __shfl_xor_sync(0xffffffffu, m, o));
                if (!lane) red[wid] = m;
            }
            __syncthreads();
            float mx = fmaxf(fmaxf(red[0], red[1]), fmaxf(red[2], red[3]));
            if (tid < 128) {
                e = expf(v - mx);
                float sme = e;
                #pragma unroll
                for (int o = 16; o; o >>= 1) sme += __shfl_xor_sync(0xffffffffu, sme, o);
                if (!lane) red[4 + wid] = sme;
            }
            __syncthreads();
            float ssum = red[4] + red[5] + red[6] + red[7];
            if (tid < 128) {
                float w = e / ssum;
                wsm[tid] = w;
                if (hc == 0) attns[((size_t)b * Tsz + t) * Ssz + tid] = w;
            }
            __syncthreads();
            const int hh = hc * 256 + tid;
            const float* Eb = enc + (size_t)b * Ssz * Hsz + hh;
            float acc = 0.f;
            #pragma unroll 8
            for (int s2 = 0; s2 < Ssz; s2++) acc = fmaf(wsm[s2], Eb[(size_t)s2 * Hsz], acc);
            x_t[b * 2 * Hsz + Hsz + hh] = acc;
        }
        grid_sync();

        // ---- E: gi_ctx partials (192 jobs) ----
        if (bid < 192) {
            int spl = bid & 7, nt = bid >> 3;
            small_core(x_t + Hsz, 2 * Hsz, W_ih + Hsz, 2 * Hsz,
                       giP + (size_t)spl * Bsz * H3, H3, spl * 128, 128, nt * 128, sm);
        }
        grid_sync();

        // ---- F: gates -> hist[t] (+fp16 copy; +out_h on final step) ----
        for (int i = gtid; i < Bsz * Hsz; i += gstride) {
            const int bb = i >> 10, jj = i & 1023;
            const int row = t * Bsz + bb;
            float gr = giemb[(size_t)row * H3 + jj];
            float gz = giemb[(size_t)row * H3 + Hsz + jj];
            float gn = giemb[(size_t)row * H3 + 2 * Hsz + jj];
            float hr = b_hh[jj], hz = b_hh[Hsz + jj], hn3 = b_hh[2 * Hsz + jj];
            const int base = bb * H3 + jj;
            #pragma unroll
            for (int p = 0; p < SPL; p++) {
                const float* gp = giP + (size_t)p * Bsz * H3 + base;
                gr += gp[0]; gz += gp[Hsz]; gn += gp[2 * Hsz];
                const float* hp = ghP + (size_t)p * Bsz * H3 + base;
                hr += hp[0]; hz += hp[Hsz]; hn3 += hp[2 * Hsz];
            }
            float r = 1.f / (1.f + expf(-(gr + hr)));
            float z = 1.f / (1.f + expf(-(gz + hz)));
            float n = tanhf(gn + r * hn3);
            float out = (1.f - z) * n + z * h[i];
            hist[(size_t)t * Bsz * Hsz + i] = out;
            g_histh[(size_t)t * Bsz * Hsz + i] = __float2half(out);
            if (t == Tsz - 1) out_h[i] = out;
        }
        grid_sync();
    }
}

// ======== init / conv / log_softmax ========
__global__ void init_k(const float* __restrict__ hidden, float* __restrict__ h0,
                       const float* __restrict__ embW, const int* __restrict__ target,
                       float* __restrict__ xall)
{
    const int idx = blockIdx.x * 256 + threadIdx.x;
    const int t = idx / (Bsz * Hsz);
    const int rem = idx - t * (Bsz * Hsz);
    const int b = rem >> 10, h = rem & 1023;
    const int tok = (t == 0) ? 0 : target[b * Tsz + (t - 1)];
    xall[(size_t)t * Bsz * 2 * Hsz + b * 2 * Hsz + h] = embW[(size_t)tok * Hsz + h];
    if (idx < Bsz * Hsz) h0[idx] = hidden[idx];
    if (idx < Bsz) g_bsync[idx] = 0u;   // reset per-launch (graph replays!)
}

__global__ void convw_k(const float* __restrict__ w, __half* __restrict__ wh)
{
    const size_t i = ((size_t)blockIdx.x * 256 + threadIdx.x) * 8;
    float4 v0 = *(const float4*)(w + i);
    float4 v1 = *(const float4*)(w + i + 4);
    __half2 h0 = __floats2half2_rn(v0.x, v0.y);
    __half2 h1 = __floats2half2_rn(v0.z, v0.w);
    __half2 h2 = __floats2half2_rn(v1.x, v1.y);
    __half2 h3 = __floats2half2_rn(v1.z, v1.w);
    uint4 pack = make_uint4(*(uint32_t*)&h0, *(uint32_t*)&h1,
                            *(uint32_t*)&h2, *(uint32_t*)&h3);
    *(uint4*)(wh + i) = pack;
}

__global__ __launch_bounds__(512)
void lsm_k(float* __restrict__ out)
{
    __shared__ float redm[16], reds[16];
    float4* p = (float4*)(out + (size_t)blockIdx.x * Vsz);
    const int NV4 = Vsz / 4;
    const int tid = threadIdx.x;

    float m = -3.4e38f, s = 0.f;
    for (int i = tid; i < NV4; i += 512) {
        float4 v = p[i];
        float m4 = fmaxf(fmaxf(v.x, v.y), fmaxf(v.z, v.w));
        float nm = fmaxf(m, m4);
        s = s * fexp(m - nm)
          + fexp(v.x - nm) + fexp(v.y - nm) + fexp(v.z - nm) + fexp(v.w - nm);
        m = nm;
    }
    #pragma unroll
    for (int o = 16; o; o >>= 1) {
        float mo = __shfl_xor_sync(0xffffffffu, m, o);
        float so = __shfl_xor_sync(0xffffffffu, s, o);
        float nm = fmaxf(m, mo);
        s = s * fexp(m - nm) + so * fexp(mo - nm);
        m = nm;
    }
    if ((tid & 31) == 0) { redm[tid >> 5] = m; reds[tid >> 5] = s; }
    __syncthreads();
    m = redm[0]; s = reds[0];
    #pragma unroll
    for (int w = 1; w < 16; w++) {
        float mo = redm[w], so = reds[w];
        float nm = fmaxf(m, mo);
        s = s * fexp(m - nm) + so * fexp(mo - nm);
        m = nm;
    }
    const float lse = m + logf(s);

    for (int i = tid; i < NV4; i += 512) {
        float4 v = p[i];
        v.x -= lse; v.y -= lse; v.z -= lse; v.w -= lse;
        p[i] = v;
    }
}

// ---------------- launch ----------------
extern "C" void kernel_launch(void* const* d_in, const int* in_sizes, int n_in,
                              void* d_out, int out_size)
{
    const float* enc    = (const float*)d_in[0];
    const float* hidden = (const float*)d_in[1];
    const int*   target = (const int*)  d_in[2];
    const float* embW   = (const float*)d_in[3];
    const float* Wa_w   = (const float*)d_in[4];
    const float* Wa_b   = (const float*)d_in[5];
    const float* Ua_w   = (const float*)d_in[6];
    const float* Ua_b   = (const float*)d_in[7];
    const float* Va_w   = (const float*)d_in[8];
    const float* Va_b   = (const float*)d_in[9];
    const float* W_ih   = (const float*)d_in[10];
    const float* W_hh   = (const float*)d_in[11];
    const float* b_ih   = (const float*)d_in[12];
    const float* b_hh   = (const float*)d_in[13];
    const float* out_W  = (const float*)d_in[14];
    const float* out_b  = (const float*)d_in[15];

    float* out_lp = (float*)d_out;                        // [B,T,V]
    float* out_h  = out_lp + (size_t)Bsz * Tsz * Vsz;     // [1,B,H]
    float* out_at = out_h + (size_t)Bsz * Hsz;            // [B,T,S]

    __half *Uk, *outWh, *histh;
    float *h0, *hist, *xall, *giemb;
    cudaGetSymbolAddress((void**)&Uk,    g_Uk);
    cudaGetSymbolAddress((void**)&outWh, g_outWh);
    cudaGetSymbolAddress((void**)&histh, g_histh);
    cudaGetSymbolAddress((void**)&h0,    g_h0);
    cudaGetSymbolAddress((void**)&hist,  g_hist);
    cudaGetSymbolAddress((void**)&xall,  g_xall);
    cudaGetSymbolAddress((void**)&giemb, g_giemb);

    cudaFuncSetAttribute(gemm_pre, cudaFuncAttributeMaxDynamicSharedMemorySize, BIG_SMEM);
    cudaFuncSetAttribute(mega_k,   cudaFuncAttributeMaxDynamicSharedMemorySize, SMALL_SMEM);

    // init: h0 + embedding gathers + g_bsync reset; out_W -> fp16
    init_k<<<(Tsz * Bsz * Hsz) / 256, 256>>>(hidden, h0, embW, target, xall);
    convw_k<<<(int)(((size_t)Vsz * Hsz) / 2048), 256>>>(out_W, outWh);

    // Uk + gi_emb merged into one launch (632 blocks, 2.1 dense waves)
    gemm_pre<<<512 + 120, 256, BIG_SMEM>>>(enc, Ua_w, Ua_b, Uk,
                                           xall, W_ih, b_ih, giemb);

    // the whole recurrence in one persistent launch; writes out_h on t=9
    mega_k<<<NBLK, 256, SMALL_SMEM>>>(enc, Wa_w, Wa_b, Va_w, Va_b,
                                      W_ih, W_hh, b_hh, out_at, out_h);

    // batched logits fp16 mma (round-11/14 proven config)
    gemm_lh<<<dim3(Vsz / 128, 1, (Tsz * Bsz) / 128), 256>>>(
        histh, outWh, out_b, out_lp);

    lsm_k<<<Bsz * Tsz, 512>>>(out_lp);
}